// round 6
// baseline (speedup 1.0000x reference)
#include <cuda_runtime.h>
#include <math.h>

#define T   2048
#define H   2048
#define E   16
#define IDIM 512
#define IS  2048

#define BM 64
#define BN 64
#define BK 16

// ---------------- scratch (static device memory; no allocation) ----------------
__device__ int   d_cnt[E];
__device__ int   d_list[E][T];        // encoded token*2 + slot
__device__ float d_wt[2 * T];         // per-assignment routing weight
__device__ float d_sg[T];             // shared-gate logit per token
__device__ float d_hmid[2 * T][IDIM]; // expert SwiGLU mid activations (8 MB)
__device__ float d_contrib[2 * T][H]; // per-assignment down-proj output (32 MB)
__device__ float d_hsh[T][IS];        // shared SwiGLU mid (16 MB)
__device__ float d_shout[T][H];       // shared down-proj output (16 MB)

// ---------------- init ----------------
__global__ void init_kernel() {
    if (threadIdx.x < E) d_cnt[threadIdx.x] = 0;
}

// ---------------- router: one warp per token ----------------
__global__ void router_kernel(const float* __restrict__ x,
                              const float* __restrict__ gw,
                              const float* __restrict__ sgw) {
    int warp = threadIdx.x >> 5, lane = threadIdx.x & 31;
    int t = blockIdx.x * (blockDim.x >> 5) + warp;
    if (t >= T) return;

    float acc[E];
#pragma unroll
    for (int e = 0; e < E; e++) acc[e] = 0.f;
    float g = 0.f;

    const float* xr = x + (size_t)t * H;
    for (int h = lane; h < H; h += 32) {
        float xv = xr[h];
        g = fmaf(xv, sgw[h], g);
#pragma unroll
        for (int e = 0; e < E; e++) acc[e] = fmaf(xv, gw[e * H + h], acc[e]);
    }
#pragma unroll
    for (int e = 0; e < E; e++) {
#pragma unroll
        for (int o = 16; o; o >>= 1) acc[e] += __shfl_xor_sync(0xffffffffu, acc[e], o);
    }
#pragma unroll
    for (int o = 16; o; o >>= 1) g += __shfl_xor_sync(0xffffffffu, g, o);

    if (lane == 0) {
        float m = acc[0];
#pragma unroll
        for (int e = 1; e < E; e++) m = fmaxf(m, acc[e]);
        float p[E];
#pragma unroll
        for (int e = 0; e < E; e++) p[e] = expf(acc[e] - m);
        // top-2 (earliest index on ties, strict >)
        int i0 = 0; float p0 = p[0];
#pragma unroll
        for (int e = 1; e < E; e++) if (p[e] > p0) { p0 = p[e]; i0 = e; }
        int i1 = -1; float p1 = -1.f;
#pragma unroll
        for (int e = 0; e < E; e++) {
            if (e == i0) continue;
            if (p[e] > p1) { p1 = p[e]; i1 = e; }
        }
        float denom = p0 + p1;                 // softmax norm cancels in the ratio
        d_wt[t * 2 + 0] = p0 / denom;
        d_wt[t * 2 + 1] = p1 / denom;
        int q0 = atomicAdd(&d_cnt[i0], 1);
        d_list[i0][q0] = t * 2 + 0;
        int q1 = atomicAdd(&d_cnt[i1], 1);
        d_list[i1][q1] = t * 2 + 1;
        d_sg[t] = g;
    }
}

// ---------------- expert up/gate (gathered rows, dual-B GLU fused) ----------------
__global__ __launch_bounds__(256)
void expert_up_kernel(const float* __restrict__ X,
                      const float* __restrict__ W1,
                      const float* __restrict__ W3) {
    int e = blockIdx.z;
    int M = d_cnt[e];
    int m0 = blockIdx.y * BM;
    if (m0 >= M) return;
    int n0 = blockIdx.x * BN;
    const float* B1 = W1 + (size_t)e * IDIM * H;
    const float* B3 = W3 + (size_t)e * IDIM * H;

    __shared__ float As[BK][BM + 4];
    __shared__ float Bs1[BK][BN + 4];
    __shared__ float Bs3[BK][BN + 4];
    __shared__ int rows[BM];

    int tid = threadIdx.x;
    if (tid < BM) {
        int m = m0 + tid;
        rows[tid] = (m < M) ? d_list[e][m] : -1;
    }
    __syncthreads();

    int lm = tid >> 2;            // 0..63
    int lk = (tid & 3) << 2;      // 0,4,8,12
    int v = rows[lm];
    bool avalid = (v >= 0);
    const float* arow = avalid ? (X + (size_t)(v >> 1) * H) : X;
    const float* b1r = B1 + (size_t)(n0 + lm) * H;
    const float* b3r = B3 + (size_t)(n0 + lm) * H;

    int ty = tid >> 4, tx = tid & 15;
    float acc1[4][4] = {}, acc3[4][4] = {};

    for (int k0 = 0; k0 < H; k0 += BK) {
        float4 av = avalid ? *(const float4*)(arow + k0 + lk) : make_float4(0, 0, 0, 0);
        float4 b1v = *(const float4*)(b1r + k0 + lk);
        float4 b3v = *(const float4*)(b3r + k0 + lk);
        As[lk + 0][lm] = av.x;  As[lk + 1][lm] = av.y;  As[lk + 2][lm] = av.z;  As[lk + 3][lm] = av.w;
        Bs1[lk + 0][lm] = b1v.x; Bs1[lk + 1][lm] = b1v.y; Bs1[lk + 2][lm] = b1v.z; Bs1[lk + 3][lm] = b1v.w;
        Bs3[lk + 0][lm] = b3v.x; Bs3[lk + 1][lm] = b3v.y; Bs3[lk + 2][lm] = b3v.z; Bs3[lk + 3][lm] = b3v.w;
        __syncthreads();
#pragma unroll
        for (int k = 0; k < BK; k++) {
            float4 a  = *(const float4*)&As[k][ty * 4];
            float4 b1 = *(const float4*)&Bs1[k][tx * 4];
            float4 b3 = *(const float4*)&Bs3[k][tx * 4];
            float aa[4] = { a.x, a.y, a.z, a.w };
            float c1[4] = { b1.x, b1.y, b1.z, b1.w };
            float c3[4] = { b3.x, b3.y, b3.z, b3.w };
#pragma unroll
            for (int i = 0; i < 4; i++)
#pragma unroll
                for (int j = 0; j < 4; j++) {
                    acc1[i][j] = fmaf(aa[i], c1[j], acc1[i][j]);
                    acc3[i][j] = fmaf(aa[i], c3[j], acc3[i][j]);
                }
        }
        __syncthreads();
    }

#pragma unroll
    for (int i = 0; i < 4; i++) {
        int vv = rows[ty * 4 + i];
        if (vv < 0) continue;
        float* dst = d_hmid[vv] + n0 + tx * 4;
#pragma unroll
        for (int j = 0; j < 4; j++) {
            float gz = acc1[i][j];
            float s = gz / (1.f + expf(-gz));
            dst[j] = s * acc3[i][j];
        }
    }
}

// ---------------- expert down (gathered rows, weighted epilogue) ----------------
__global__ __launch_bounds__(256)
void expert_down_kernel(const float* __restrict__ W2) {
    int e = blockIdx.z;
    int M = d_cnt[e];
    int m0 = blockIdx.y * BM;
    if (m0 >= M) return;
    int n0 = blockIdx.x * BN;
    const float* B = W2 + (size_t)e * H * IDIM;

    __shared__ float As[BK][BM + 4];
    __shared__ float Bs[BK][BN + 4];
    __shared__ int rows[BM];

    int tid = threadIdx.x;
    if (tid < BM) {
        int m = m0 + tid;
        rows[tid] = (m < M) ? d_list[e][m] : -1;
    }
    __syncthreads();

    int lm = tid >> 2;
    int lk = (tid & 3) << 2;
    int v = rows[lm];
    bool avalid = (v >= 0);
    const float* arow = avalid ? d_hmid[v] : d_hmid[0];
    const float* br = B + (size_t)(n0 + lm) * IDIM;

    int ty = tid >> 4, tx = tid & 15;
    float acc[4][4] = {};

    for (int k0 = 0; k0 < IDIM; k0 += BK) {
        float4 av = avalid ? *(const float4*)(arow + k0 + lk) : make_float4(0, 0, 0, 0);
        float4 bv = *(const float4*)(br + k0 + lk);
        As[lk + 0][lm] = av.x; As[lk + 1][lm] = av.y; As[lk + 2][lm] = av.z; As[lk + 3][lm] = av.w;
        Bs[lk + 0][lm] = bv.x; Bs[lk + 1][lm] = bv.y; Bs[lk + 2][lm] = bv.z; Bs[lk + 3][lm] = bv.w;
        __syncthreads();
#pragma unroll
        for (int k = 0; k < BK; k++) {
            float4 a = *(const float4*)&As[k][ty * 4];
            float4 b = *(const float4*)&Bs[k][tx * 4];
            float aa[4] = { a.x, a.y, a.z, a.w };
            float bb[4] = { b.x, b.y, b.z, b.w };
#pragma unroll
            for (int i = 0; i < 4; i++)
#pragma unroll
                for (int j = 0; j < 4; j++)
                    acc[i][j] = fmaf(aa[i], bb[j], acc[i][j]);
        }
        __syncthreads();
    }

#pragma unroll
    for (int i = 0; i < 4; i++) {
        int vv = rows[ty * 4 + i];
        if (vv < 0) continue;
        float w = d_wt[vv];
        float* dst = d_contrib[vv] + n0 + tx * 4;
#pragma unroll
        for (int j = 0; j < 4; j++) dst[j] = w * acc[i][j];
    }
}

// ---------------- shared expert up/gate (dense, dual-B GLU fused) ----------------
__global__ __launch_bounds__(256)
void shared_up_kernel(const float* __restrict__ X,
                      const float* __restrict__ Wg,
                      const float* __restrict__ Wu) {
    int m0 = blockIdx.y * BM;
    int n0 = blockIdx.x * BN;

    __shared__ float As[BK][BM + 4];
    __shared__ float Bs1[BK][BN + 4];
    __shared__ float Bs3[BK][BN + 4];

    int tid = threadIdx.x;
    int lm = tid >> 2;
    int lk = (tid & 3) << 2;
    const float* arow = X + (size_t)(m0 + lm) * H;
    const float* b1r = Wg + (size_t)(n0 + lm) * H;
    const float* b3r = Wu + (size_t)(n0 + lm) * H;

    int ty = tid >> 4, tx = tid & 15;
    float acc1[4][4] = {}, acc3[4][4] = {};

    for (int k0 = 0; k0 < H; k0 += BK) {
        float4 av = *(const float4*)(arow + k0 + lk);
        float4 b1v = *(const float4*)(b1r + k0 + lk);
        float4 b3v = *(const float4*)(b3r + k0 + lk);
        As[lk + 0][lm] = av.x;  As[lk + 1][lm] = av.y;  As[lk + 2][lm] = av.z;  As[lk + 3][lm] = av.w;
        Bs1[lk + 0][lm] = b1v.x; Bs1[lk + 1][lm] = b1v.y; Bs1[lk + 2][lm] = b1v.z; Bs1[lk + 3][lm] = b1v.w;
        Bs3[lk + 0][lm] = b3v.x; Bs3[lk + 1][lm] = b3v.y; Bs3[lk + 2][lm] = b3v.z; Bs3[lk + 3][lm] = b3v.w;
        __syncthreads();
#pragma unroll
        for (int k = 0; k < BK; k++) {
            float4 a  = *(const float4*)&As[k][ty * 4];
            float4 b1 = *(const float4*)&Bs1[k][tx * 4];
            float4 b3 = *(const float4*)&Bs3[k][tx * 4];
            float aa[4] = { a.x, a.y, a.z, a.w };
            float c1[4] = { b1.x, b1.y, b1.z, b1.w };
            float c3[4] = { b3.x, b3.y, b3.z, b3.w };
#pragma unroll
            for (int i = 0; i < 4; i++)
#pragma unroll
                for (int j = 0; j < 4; j++) {
                    acc1[i][j] = fmaf(aa[i], c1[j], acc1[i][j]);
                    acc3[i][j] = fmaf(aa[i], c3[j], acc3[i][j]);
                }
        }
        __syncthreads();
    }

#pragma unroll
    for (int i = 0; i < 4; i++) {
        int m = m0 + ty * 4 + i;
        float* dst = d_hsh[m] + n0 + tx * 4;
#pragma unroll
        for (int j = 0; j < 4; j++) {
            float gz = acc1[i][j];
            float s = gz / (1.f + expf(-gz));
            dst[j] = s * acc3[i][j];
        }
    }
}

// ---------------- shared expert down ----------------
__global__ __launch_bounds__(256)
void shared_down_kernel(const float* __restrict__ Wd) {
    int m0 = blockIdx.y * BM;
    int n0 = blockIdx.x * BN;

    __shared__ float As[BK][BM + 4];
    __shared__ float Bs[BK][BN + 4];

    int tid = threadIdx.x;
    int lm = tid >> 2;
    int lk = (tid & 3) << 2;
    const float* arow = d_hsh[m0 + lm];
    const float* br = Wd + (size_t)(n0 + lm) * IS;

    int ty = tid >> 4, tx = tid & 15;
    float acc[4][4] = {};

    for (int k0 = 0; k0 < IS; k0 += BK) {
        float4 av = *(const float4*)(arow + k0 + lk);
        float4 bv = *(const float4*)(br + k0 + lk);
        As[lk + 0][lm] = av.x; As[lk + 1][lm] = av.y; As[lk + 2][lm] = av.z; As[lk + 3][lm] = av.w;
        Bs[lk + 0][lm] = bv.x; Bs[lk + 1][lm] = bv.y; Bs[lk + 2][lm] = bv.z; Bs[lk + 3][lm] = bv.w;
        __syncthreads();
#pragma unroll
        for (int k = 0; k < BK; k++) {
            float4 a = *(const float4*)&As[k][ty * 4];
            float4 b = *(const float4*)&Bs[k][tx * 4];
            float aa[4] = { a.x, a.y, a.z, a.w };
            float bb[4] = { b.x, b.y, b.z, b.w };
#pragma unroll
            for (int i = 0; i < 4; i++)
#pragma unroll
                for (int j = 0; j < 4; j++)
                    acc[i][j] = fmaf(aa[i], bb[j], acc[i][j]);
        }
        __syncthreads();
    }

#pragma unroll
    for (int i = 0; i < 4; i++) {
        int m = m0 + ty * 4 + i;
        float* dst = d_shout[m] + n0 + tx * 4;
#pragma unroll
        for (int j = 0; j < 4; j++) dst[j] = acc[i][j];
    }
}

// ---------------- combine ----------------
__global__ void combine_kernel(float* __restrict__ out) {
    int i = blockIdx.x * blockDim.x + threadIdx.x;   // float4 index over T*H/4
    int t = i / (H / 4);
    int c = (i % (H / 4)) * 4;
    float4 a = *(const float4*)&d_contrib[2 * t + 0][c];
    float4 b = *(const float4*)&d_contrib[2 * t + 1][c];
    float4 s = *(const float4*)&d_shout[t][c];
    float sg = 1.f / (1.f + expf(-d_sg[t]));
    float4 o;
    o.x = a.x + b.x + sg * s.x;
    o.y = a.y + b.y + sg * s.y;
    o.z = a.z + b.z + sg * s.z;
    o.w = a.w + b.w + sg * s.w;
    ((float4*)out)[i] = o;
}

// ---------------- launch ----------------
extern "C" void kernel_launch(void* const* d_in, const int* in_sizes, int n_in,
                              void* d_out, int out_size) {
    (void)in_sizes; (void)n_in; (void)out_size;
    const float* x        = (const float*)d_in[0];
    const float* gate_w   = (const float*)d_in[1];
    const float* w1       = (const float*)d_in[2];
    const float* w2       = (const float*)d_in[3];
    const float* w3       = (const float*)d_in[4];
    const float* ws_gate  = (const float*)d_in[5];
    const float* ws_up    = (const float*)d_in[6];
    const float* ws_down  = (const float*)d_in[7];
    const float* sgw      = (const float*)d_in[8];
    float* out = (float*)d_out;

    init_kernel<<<1, 32>>>();
    router_kernel<<<T / 4, 128>>>(x, gate_w, sgw);
    expert_up_kernel<<<dim3(IDIM / BN, T / BM, E), 256>>>(x, w1, w3);
    expert_down_kernel<<<dim3(H / BN, T / BM, E), 256>>>(w2);
    shared_up_kernel<<<dim3(IS / BN, T / BM), 256>>>(x, ws_gate, ws_up);
    shared_down_kernel<<<dim3(H / BN, T / BM), 256>>>(ws_down);
    combine_kernel<<<(T * H / 4) / 256, 256>>>(out);
}

// round 10
// speedup vs baseline: 2.7314x; 2.7314x over previous
#include <cuda_runtime.h>
#include <math.h>
#include <stdint.h>

#define T   2048
#define H   2048
#define E   16
#define IDIM 512
#define IS  2048

#define PAD 36   // smem row stride (floats): 4*gid+tig -> conflict-free frag loads

// ---------------- scratch (static device memory; no allocation) ----------------
__device__ int   d_cnt[E];
__device__ int   d_list[E][T];        // encoded token*2 + slot
__device__ float d_wt[2 * T];         // per-assignment routing weight
__device__ float d_sg[T];             // shared-gate logit per token
__device__ float d_hmid[2 * T][IDIM]; // expert SwiGLU mid activations
__device__ float d_contrib[2 * T][H]; // per-assignment down-proj output
__device__ float d_hsh[T][IS];        // shared SwiGLU mid
__device__ float d_shout[T][H];       // shared down-proj output

// ---------------- helpers ----------------
__device__ __forceinline__ uint32_t f2tf(float f) {
    uint32_t u;
    asm("cvt.rna.tf32.f32 %0, %1;" : "=r"(u) : "f"(f));
    return u;
}
__device__ __forceinline__ void st4(uint32_t* p, float4 v) {
    p[0] = f2tf(v.x); p[1] = f2tf(v.y); p[2] = f2tf(v.z); p[3] = f2tf(v.w);
}
__device__ __forceinline__ void mma8(float c[4], const uint32_t a[4], const uint32_t b[2]) {
    asm volatile(
        "mma.sync.aligned.m16n8k8.row.col.f32.tf32.tf32.f32 "
        "{%0,%1,%2,%3}, {%4,%5,%6,%7}, {%8,%9}, {%0,%1,%2,%3};"
        : "+f"(c[0]), "+f"(c[1]), "+f"(c[2]), "+f"(c[3])
        : "r"(a[0]), "r"(a[1]), "r"(a[2]), "r"(a[3]), "r"(b[0]), "r"(b[1]));
}
__device__ __forceinline__ float silu_f(float x) { return x / (1.f + expf(-x)); }

// ---------------- init ----------------
__global__ void init_kernel() {
    if (threadIdx.x < E) d_cnt[threadIdx.x] = 0;
}

// ---------------- router: one warp per token (fp32, unchanged) ----------------
__global__ void router_kernel(const float* __restrict__ x,
                              const float* __restrict__ gw,
                              const float* __restrict__ sgw) {
    int warp = threadIdx.x >> 5, lane = threadIdx.x & 31;
    int t = blockIdx.x * (blockDim.x >> 5) + warp;
    if (t >= T) return;

    float acc[E];
#pragma unroll
    for (int e = 0; e < E; e++) acc[e] = 0.f;
    float g = 0.f;

    const float* xr = x + (size_t)t * H;
    for (int h = lane; h < H; h += 32) {
        float xv = xr[h];
        g = fmaf(xv, sgw[h], g);
#pragma unroll
        for (int e = 0; e < E; e++) acc[e] = fmaf(xv, gw[e * H + h], acc[e]);
    }
#pragma unroll
    for (int e = 0; e < E; e++) {
#pragma unroll
        for (int o = 16; o; o >>= 1) acc[e] += __shfl_xor_sync(0xffffffffu, acc[e], o);
    }
#pragma unroll
    for (int o = 16; o; o >>= 1) g += __shfl_xor_sync(0xffffffffu, g, o);

    if (lane == 0) {
        float m = acc[0];
#pragma unroll
        for (int e = 1; e < E; e++) m = fmaxf(m, acc[e]);
        float p[E];
#pragma unroll
        for (int e = 0; e < E; e++) p[e] = expf(acc[e] - m);
        int i0 = 0; float p0 = p[0];
#pragma unroll
        for (int e = 1; e < E; e++) if (p[e] > p0) { p0 = p[e]; i0 = e; }
        int i1 = -1; float p1 = -1.f;
#pragma unroll
        for (int e = 0; e < E; e++) {
            if (e == i0) continue;
            if (p[e] > p1) { p1 = p[e]; i1 = e; }
        }
        float denom = p0 + p1;
        d_wt[t * 2 + 0] = p0 / denom;
        d_wt[t * 2 + 1] = p1 / denom;
        int q0 = atomicAdd(&d_cnt[i0], 1);
        d_list[i0][q0] = t * 2 + 0;
        int q1 = atomicAdd(&d_cnt[i1], 1);
        d_list[i1][q1] = t * 2 + 1;
        d_sg[t] = g;
    }
}

// =================================================================
// expert up/gate: tf32 MMA, BM=128 BN=64 BK=32, dual-B GLU fused
// grid (IDIM/64, T/128, E), 256 threads
// =================================================================
__global__ __launch_bounds__(256)
void expert_up_mma(const float* __restrict__ X,
                   const float* __restrict__ W1,
                   const float* __restrict__ W3) {
    int e = blockIdx.z;
    int M = d_cnt[e];
    int m0 = blockIdx.y * 128;
    if (m0 >= M) return;
    int n0 = blockIdx.x * 64;
    const float* B1 = W1 + (size_t)e * IDIM * H;
    const float* B3 = W3 + (size_t)e * IDIM * H;

    __shared__ uint32_t As[128][PAD];
    __shared__ uint32_t Bs1[64][PAD];
    __shared__ uint32_t Bs3[64][PAD];
    __shared__ int rows[128];

    int tid = threadIdx.x;
    if (tid < 128) { int m = m0 + tid; rows[tid] = (m < M) ? d_list[e][m] : -1; }
    __syncthreads();

    int lr = tid >> 3;          // 0..31
    int lc = (tid & 7) << 2;    // 0,4,...,28
    const float* arow[4]; bool av[4];
#pragma unroll
    for (int p = 0; p < 4; p++) {
        int enc = rows[lr + 32 * p];
        av[p] = enc >= 0;
        arow[p] = av[p] ? X + (size_t)(enc >> 1) * H + lc : X;
    }
    const float* b1r[2] = { B1 + (size_t)(n0 + lr) * H + lc, B1 + (size_t)(n0 + lr + 32) * H + lc };
    const float* b3r[2] = { B3 + (size_t)(n0 + lr) * H + lc, B3 + (size_t)(n0 + lr + 32) * H + lc };

    int warp = tid >> 5, lane = tid & 31;
    int wm = (warp & 3) << 5;       // 0,32,64,96
    int wn = (warp >> 2) << 5;      // 0,32
    int gid = lane >> 2, tig = lane & 3;

    float acc1[2][4][4] = {};
    float acc3[2][4][4] = {};

    float4 pa[4], pb1[2], pb3[2];
#pragma unroll
    for (int p = 0; p < 4; p++) pa[p] = av[p] ? *(const float4*)(arow[p]) : make_float4(0, 0, 0, 0);
#pragma unroll
    for (int p = 0; p < 2; p++) { pb1[p] = *(const float4*)(b1r[p]); pb3[p] = *(const float4*)(b3r[p]); }

    for (int k0 = 0; k0 < H; k0 += 32) {
#pragma unroll
        for (int p = 0; p < 4; p++) st4(&As[lr + 32 * p][lc], pa[p]);
#pragma unroll
        for (int p = 0; p < 2; p++) {
            st4(&Bs1[lr + 32 * p][lc], pb1[p]);
            st4(&Bs3[lr + 32 * p][lc], pb3[p]);
        }
        __syncthreads();
        if (k0 + 32 < H) {
            int off = k0 + 32;
#pragma unroll
            for (int p = 0; p < 4; p++) pa[p] = av[p] ? *(const float4*)(arow[p] + off) : make_float4(0, 0, 0, 0);
#pragma unroll
            for (int p = 0; p < 2; p++) { pb1[p] = *(const float4*)(b1r[p] + off); pb3[p] = *(const float4*)(b3r[p] + off); }
        }
#pragma unroll
        for (int ks = 0; ks < 4; ks++) {
            int kk = ks * 8;
            uint32_t a[2][4];
#pragma unroll
            for (int mi = 0; mi < 2; mi++) {
                int r0 = wm + mi * 16 + gid;
                a[mi][0] = As[r0][kk + tig];
                a[mi][1] = As[r0 + 8][kk + tig];
                a[mi][2] = As[r0][kk + tig + 4];
                a[mi][3] = As[r0 + 8][kk + tig + 4];
            }
#pragma unroll
            for (int ni = 0; ni < 4; ni++) {
                int rb = wn + ni * 8 + gid;
                uint32_t b1f[2] = { Bs1[rb][kk + tig], Bs1[rb][kk + tig + 4] };
                uint32_t b3f[2] = { Bs3[rb][kk + tig], Bs3[rb][kk + tig + 4] };
#pragma unroll
                for (int mi = 0; mi < 2; mi++) {
                    mma8(acc1[mi][ni], a[mi], b1f);
                    mma8(acc3[mi][ni], a[mi], b3f);
                }
            }
        }
        __syncthreads();
    }

#pragma unroll
    for (int mi = 0; mi < 2; mi++) {
#pragma unroll
        for (int hh = 0; hh < 2; hh++) {
            int r = wm + mi * 16 + gid + 8 * hh;
            int enc = rows[r];
            if (enc < 0) continue;
            float* dst = d_hmid[enc] + n0 + wn + tig * 2;
#pragma unroll
            for (int ni = 0; ni < 4; ni++) {
                float g0 = acc1[mi][ni][2 * hh], g1 = acc1[mi][ni][2 * hh + 1];
                float u0 = acc3[mi][ni][2 * hh], u1 = acc3[mi][ni][2 * hh + 1];
                float2 v = make_float2(silu_f(g0) * u0, silu_f(g1) * u1);
                *(float2*)(dst + ni * 8) = v;
            }
        }
    }
}

// =================================================================
// expert down: tf32 MMA, BM=128 BN=128 BK=32, single-B, weighted epi
// grid (H/128, T/128, E), 256 threads
// =================================================================
__global__ __launch_bounds__(256)
void expert_down_mma(const float* __restrict__ W2) {
    int e = blockIdx.z;
    int M = d_cnt[e];
    int m0 = blockIdx.y * 128;
    if (m0 >= M) return;
    int n0 = blockIdx.x * 128;
    const float* B = W2 + (size_t)e * H * IDIM;

    __shared__ uint32_t As[128][PAD];
    __shared__ uint32_t Bs[128][PAD];
    __shared__ int rows[128];

    int tid = threadIdx.x;
    if (tid < 128) { int m = m0 + tid; rows[tid] = (m < M) ? d_list[e][m] : -1; }
    __syncthreads();

    int lr = tid >> 3;
    int lc = (tid & 7) << 2;
    const float* arow[4]; bool av[4];
#pragma unroll
    for (int p = 0; p < 4; p++) {
        int enc = rows[lr + 32 * p];
        av[p] = enc >= 0;
        arow[p] = av[p] ? d_hmid[enc] + lc : d_hmid[0];
    }
    const float* brow[4];
#pragma unroll
    for (int p = 0; p < 4; p++) brow[p] = B + (size_t)(n0 + lr + 32 * p) * IDIM + lc;

    int warp = tid >> 5, lane = tid & 31;
    int wm = (warp & 3) << 5;
    int wn = (warp >> 2) << 6;   // 0,64
    int gid = lane >> 2, tig = lane & 3;

    float acc[2][8][4] = {};

    float4 pa[4], pb[4];
#pragma unroll
    for (int p = 0; p < 4; p++) {
        pa[p] = av[p] ? *(const float4*)(arow[p]) : make_float4(0, 0, 0, 0);
        pb[p] = *(const float4*)(brow[p]);
    }

    for (int k0 = 0; k0 < IDIM; k0 += 32) {
#pragma unroll
        for (int p = 0; p < 4; p++) {
            st4(&As[lr + 32 * p][lc], pa[p]);
            st4(&Bs[lr + 32 * p][lc], pb[p]);
        }
        __syncthreads();
        if (k0 + 32 < IDIM) {
            int off = k0 + 32;
#pragma unroll
            for (int p = 0; p < 4; p++) {
                pa[p] = av[p] ? *(const float4*)(arow[p] + off) : make_float4(0, 0, 0, 0);
                pb[p] = *(const float4*)(brow[p] + off);
            }
        }
#pragma unroll
        for (int ks = 0; ks < 4; ks++) {
            int kk = ks * 8;
            uint32_t a[2][4];
#pragma unroll
            for (int mi = 0; mi < 2; mi++) {
                int r0 = wm + mi * 16 + gid;
                a[mi][0] = As[r0][kk + tig];
                a[mi][1] = As[r0 + 8][kk + tig];
                a[mi][2] = As[r0][kk + tig + 4];
                a[mi][3] = As[r0 + 8][kk + tig + 4];
            }
#pragma unroll
            for (int ni = 0; ni < 8; ni++) {
                int rb = wn + ni * 8 + gid;
                uint32_t bf[2] = { Bs[rb][kk + tig], Bs[rb][kk + tig + 4] };
#pragma unroll
                for (int mi = 0; mi < 2; mi++) mma8(acc[mi][ni], a[mi], bf);
            }
        }
        __syncthreads();
    }

#pragma unroll
    for (int mi = 0; mi < 2; mi++) {
#pragma unroll
        for (int hh = 0; hh < 2; hh++) {
            int r = wm + mi * 16 + gid + 8 * hh;
            int enc = rows[r];
            if (enc < 0) continue;
            float w = d_wt[enc];
            float* dst = d_contrib[enc] + n0 + wn + tig * 2;
#pragma unroll
            for (int ni = 0; ni < 8; ni++) {
                float2 v = make_float2(w * acc[mi][ni][2 * hh], w * acc[mi][ni][2 * hh + 1]);
                *(float2*)(dst + ni * 8) = v;
            }
        }
    }
}

// =================================================================
// shared up/gate: dense, tf32 MMA, BM=128 BN=64 BK=32, dual-B GLU
// grid (IS/64, T/128), 256 threads
// =================================================================
__global__ __launch_bounds__(256)
void shared_up_mma(const float* __restrict__ X,
                   const float* __restrict__ Wg,
                   const float* __restrict__ Wu) {
    int m0 = blockIdx.y * 128;
    int n0 = blockIdx.x * 64;

    __shared__ uint32_t As[128][PAD];
    __shared__ uint32_t Bs1[64][PAD];
    __shared__ uint32_t Bs3[64][PAD];

    int tid = threadIdx.x;
    int lr = tid >> 3;
    int lc = (tid & 7) << 2;
    const float* arow[4];
#pragma unroll
    for (int p = 0; p < 4; p++) arow[p] = X + (size_t)(m0 + lr + 32 * p) * H + lc;
    const float* b1r[2] = { Wg + (size_t)(n0 + lr) * H + lc, Wg + (size_t)(n0 + lr + 32) * H + lc };
    const float* b3r[2] = { Wu + (size_t)(n0 + lr) * H + lc, Wu + (size_t)(n0 + lr + 32) * H + lc };

    int warp = tid >> 5, lane = tid & 31;
    int wm = (warp & 3) << 5;
    int wn = (warp >> 2) << 5;
    int gid = lane >> 2, tig = lane & 3;

    float acc1[2][4][4] = {};
    float acc3[2][4][4] = {};

    float4 pa[4], pb1[2], pb3[2];
#pragma unroll
    for (int p = 0; p < 4; p++) pa[p] = *(const float4*)(arow[p]);
#pragma unroll
    for (int p = 0; p < 2; p++) { pb1[p] = *(const float4*)(b1r[p]); pb3[p] = *(const float4*)(b3r[p]); }

    for (int k0 = 0; k0 < H; k0 += 32) {
#pragma unroll
        for (int p = 0; p < 4; p++) st4(&As[lr + 32 * p][lc], pa[p]);
#pragma unroll
        for (int p = 0; p < 2; p++) {
            st4(&Bs1[lr + 32 * p][lc], pb1[p]);
            st4(&Bs3[lr + 32 * p][lc], pb3[p]);
        }
        __syncthreads();
        if (k0 + 32 < H) {
            int off = k0 + 32;
#pragma unroll
            for (int p = 0; p < 4; p++) pa[p] = *(const float4*)(arow[p] + off);
#pragma unroll
            for (int p = 0; p < 2; p++) { pb1[p] = *(const float4*)(b1r[p] + off); pb3[p] = *(const float4*)(b3r[p] + off); }
        }
#pragma unroll
        for (int ks = 0; ks < 4; ks++) {
            int kk = ks * 8;
            uint32_t a[2][4];
#pragma unroll
            for (int mi = 0; mi < 2; mi++) {
                int r0 = wm + mi * 16 + gid;
                a[mi][0] = As[r0][kk + tig];
                a[mi][1] = As[r0 + 8][kk + tig];
                a[mi][2] = As[r0][kk + tig + 4];
                a[mi][3] = As[r0 + 8][kk + tig + 4];
            }
#pragma unroll
            for (int ni = 0; ni < 4; ni++) {
                int rb = wn + ni * 8 + gid;
                uint32_t b1f[2] = { Bs1[rb][kk + tig], Bs1[rb][kk + tig + 4] };
                uint32_t b3f[2] = { Bs3[rb][kk + tig], Bs3[rb][kk + tig + 4] };
#pragma unroll
                for (int mi = 0; mi < 2; mi++) {
                    mma8(acc1[mi][ni], a[mi], b1f);
                    mma8(acc3[mi][ni], a[mi], b3f);
                }
            }
        }
        __syncthreads();
    }

#pragma unroll
    for (int mi = 0; mi < 2; mi++) {
#pragma unroll
        for (int hh = 0; hh < 2; hh++) {
            int r = m0 + wm + mi * 16 + gid + 8 * hh;
            float* dst = d_hsh[r] + n0 + wn + tig * 2;
#pragma unroll
            for (int ni = 0; ni < 4; ni++) {
                float g0 = acc1[mi][ni][2 * hh], g1 = acc1[mi][ni][2 * hh + 1];
                float u0 = acc3[mi][ni][2 * hh], u1 = acc3[mi][ni][2 * hh + 1];
                float2 v = make_float2(silu_f(g0) * u0, silu_f(g1) * u1);
                *(float2*)(dst + ni * 8) = v;
            }
        }
    }
}

// =================================================================
// shared down: dense, tf32 MMA, BM=128 BN=128 BK=32, single-B
// grid (H/128, T/128), 256 threads
// =================================================================
__global__ __launch_bounds__(256)
void shared_down_mma(const float* __restrict__ Wd) {
    int m0 = blockIdx.y * 128;
    int n0 = blockIdx.x * 128;

    __shared__ uint32_t As[128][PAD];
    __shared__ uint32_t Bs[128][PAD];

    int tid = threadIdx.x;
    int lr = tid >> 3;
    int lc = (tid & 7) << 2;
    const float* arow[4];
    const float* brow[4];
#pragma unroll
    for (int p = 0; p < 4; p++) {
        arow[p] = d_hsh[m0 + lr + 32 * p] + lc;
        brow[p] = Wd + (size_t)(n0 + lr + 32 * p) * IS + lc;
    }

    int warp = tid >> 5, lane = tid & 31;
    int wm = (warp & 3) << 5;
    int wn = (warp >> 2) << 6;
    int gid = lane >> 2, tig = lane & 3;

    float acc[2][8][4] = {};

    float4 pa[4], pb[4];
#pragma unroll
    for (int p = 0; p < 4; p++) { pa[p] = *(const float4*)(arow[p]); pb[p] = *(const float4*)(brow[p]); }

    for (int k0 = 0; k0 < IS; k0 += 32) {
#pragma unroll
        for (int p = 0; p < 4; p++) {
            st4(&As[lr + 32 * p][lc], pa[p]);
            st4(&Bs[lr + 32 * p][lc], pb[p]);
        }
        __syncthreads();
        if (k0 + 32 < IS) {
            int off = k0 + 32;
#pragma unroll
            for (int p = 0; p < 4; p++) { pa[p] = *(const float4*)(arow[p] + off); pb[p] = *(const float4*)(brow[p] + off); }
        }
#pragma unroll
        for (int ks = 0; ks < 4; ks++) {
            int kk = ks * 8;
            uint32_t a[2][4];
#pragma unroll
            for (int mi = 0; mi < 2; mi++) {
                int r0 = wm + mi * 16 + gid;
                a[mi][0] = As[r0][kk + tig];
                a[mi][1] = As[r0 + 8][kk + tig];
                a[mi][2] = As[r0][kk + tig + 4];
                a[mi][3] = As[r0 + 8][kk + tig + 4];
            }
#pragma unroll
            for (int ni = 0; ni < 8; ni++) {
                int rb = wn + ni * 8 + gid;
                uint32_t bf[2] = { Bs[rb][kk + tig], Bs[rb][kk + tig + 4] };
#pragma unroll
                for (int mi = 0; mi < 2; mi++) mma8(acc[mi][ni], a[mi], bf);
            }
        }
        __syncthreads();
    }

#pragma unroll
    for (int mi = 0; mi < 2; mi++) {
#pragma unroll
        for (int hh = 0; hh < 2; hh++) {
            int r = m0 + wm + mi * 16 + gid + 8 * hh;
            float* dst = d_shout[r] + n0 + wn + tig * 2;
#pragma unroll
            for (int ni = 0; ni < 8; ni++) {
                float2 v = make_float2(acc[mi][ni][2 * hh], acc[mi][ni][2 * hh + 1]);
                *(float2*)(dst + ni * 8) = v;
            }
        }
    }
}

// ---------------- combine ----------------
__global__ void combine_kernel(float* __restrict__ out) {
    int i = blockIdx.x * blockDim.x + threadIdx.x;   // float4 index over T*H/4
    int t = i / (H / 4);
    int c = (i % (H / 4)) * 4;
    float4 a = *(const float4*)&d_contrib[2 * t + 0][c];
    float4 b = *(const float4*)&d_contrib[2 * t + 1][c];
    float4 s = *(const float4*)&d_shout[t][c];
    float sg = 1.f / (1.f + expf(-d_sg[t]));
    float4 o;
    o.x = a.x + b.x + sg * s.x;
    o.y = a.y + b.y + sg * s.y;
    o.z = a.z + b.z + sg * s.z;
    o.w = a.w + b.w + sg * s.w;
    ((float4*)out)[i] = o;
}

// ---------------- launch ----------------
extern "C" void kernel_launch(void* const* d_in, const int* in_sizes, int n_in,
                              void* d_out, int out_size) {
    (void)in_sizes; (void)n_in; (void)out_size;
    const float* x        = (const float*)d_in[0];
    const float* gate_w   = (const float*)d_in[1];
    const float* w1       = (const float*)d_in[2];
    const float* w2       = (const float*)d_in[3];
    const float* w3       = (const float*)d_in[4];
    const float* ws_gate  = (const float*)d_in[5];
    const float* ws_up    = (const float*)d_in[6];
    const float* ws_down  = (const float*)d_in[7];
    const float* sgw      = (const float*)d_in[8];
    float* out = (float*)d_out;

    init_kernel<<<1, 32>>>();
    router_kernel<<<T / 4, 128>>>(x, gate_w, sgw);
    expert_up_mma<<<dim3(IDIM / 64, T / 128, E), 256>>>(x, w1, w3);
    expert_down_mma<<<dim3(H / 128, T / 128, E), 256>>>(w2);
    shared_up_mma<<<dim3(IS / 64, T / 128), 256>>>(x, ws_gate, ws_up);
    shared_down_mma<<<dim3(H / 128, T / 128), 256>>>(ws_down);
    combine_kernel<<<(T * H / 4) / 256, 256>>>(out);
}